// round 12
// baseline (speedup 1.0000x reference)
#include <cuda_runtime.h>
#include <cstdint>

#define DD 32
#define HH 64
#define NB 4096
#define EPSF 1e-10f
#define BSTRIDE 33
#define PGRID 820   // persistent grid: <= 6 blocks/SM * 148 SMs, all resident

// Scratch (allocation-free rule: __device__ globals)
__device__ float g_V[(size_t)NB * DD * HH];   // [r][i][h]  33.5 MB
__device__ float g_CA[NB * HH];               // [r][h]
__device__ int   g_off[NB + 1];

typedef unsigned long long u64;

__device__ __forceinline__ u64 fma2(u64 a, u64 b, u64 c) {
    u64 d; asm("fma.rn.f32x2 %0, %1, %2, %3;" : "=l"(d) : "l"(a), "l"(b), "l"(c)); return d;
}
__device__ __forceinline__ u64 add2(u64 a, u64 b) {
    u64 d; asm("add.rn.f32x2 %0, %1, %2;" : "=l"(d) : "l"(a), "l"(b)); return d;
}
__device__ __forceinline__ u64 pack2(float lo, float hi) {
    u64 d; asm("mov.b64 %0, {%1, %2};" : "=l"(d) : "f"(lo), "f"(hi)); return d;
}
__device__ __forceinline__ void unpack2(u64 a, float& lo, float& hi) {
    asm("mov.b64 {%0, %1}, %2;" : "=f"(lo), "=f"(hi) : "l"(a));
}
__device__ __forceinline__ float tanh_approx(float x) {
    float y; asm("tanh.approx.f32 %0, %1;" : "=f"(y) : "f"(x)); return y;
}
__device__ __forceinline__ uint32_t s2u(const void* p) {
    uint32_t a;
    asm("{ .reg .u64 t; cvta.to.shared.u64 t, %1; cvt.u32.u64 %0, t; }" : "=r"(a) : "l"(p));
    return a;
}
__device__ __forceinline__ void cpa16(uint32_t d, const void* s) {
    asm volatile("cp.async.cg.shared.global [%0], [%1], 16;" :: "r"(d), "l"(s));
}
__device__ __forceinline__ void cpa4(uint32_t d, const void* s) {
    asm volatile("cp.async.ca.shared.global [%0], [%1], 4;" :: "r"(d), "l"(s));
}
#define CP_COMMIT() asm volatile("cp.async.commit_group;" ::: "memory")
#define CP_WAIT0()  asm volatile("cp.async.wait_group 0;"  ::: "memory")

// ---------------------------------------------------------------------------
// Kernel C: segment offsets from sorted row_ids (vectorized parallel scatter).
// g_off[q] = lower_bound(row_ids, q)
// ---------------------------------------------------------------------------
__global__ void build_offsets(const int* __restrict__ row_ids, int T) {
    int t0 = (blockIdx.x * blockDim.x + threadIdx.x) * 4;
    if (t0 >= T) return;
    int prev = (t0 == 0) ? -1 : __ldg(&row_ids[t0 - 1]);
    #pragma unroll
    for (int k = 0; k < 4; k++) {
        int t = t0 + k;
        if (t >= T) break;
        int cur = __ldg(&row_ids[t]);
        for (int q = prev + 1; q <= cur; q++) g_off[q] = t;
        prev = cur;
        if (t == T - 1)
            for (int q = cur + 1; q <= NB; q++) g_off[q] = T;
    }
}

// ---------------------------------------------------------------------------
// Kernel A: per-candidate precompute (unchanged).
// ---------------------------------------------------------------------------
__global__ void __launch_bounds__(128) precompute_V(
    const float* __restrict__ cand,
    const float* __restrict__ W1,
    const float* __restrict__ b1)
{
    __shared__ __align__(16) float cs[32 * 32];
    int rt  = blockIdx.x;
    int nt  = blockIdx.y;
    int tid = threadIdx.x;

    const float4* csrc = (const float4*)(cand + (size_t)rt * 32 * DD);
    float4* cdst = (float4*)cs;
    cdst[tid]       = csrc[tid];
    cdst[tid + 128] = csrc[tid + 128];
    __syncthreads();

    if (nt < 16) {
        int n = nt * 128 + tid;          // n = i*64 + h
        int i = n >> 6, h = n & 63;
        const float* wbase = W1 + (size_t)(64 + i * 32) * HH + h;

        u64 acc2[32];
        #pragma unroll
        for (int rr = 0; rr < 32; rr++) acc2[rr] = 0ull;

        #pragma unroll
        for (int j4 = 0; j4 < 8; j4++) {
            float w0  = wbase[(j4 * 4 + 0) * HH];
            float w1v = wbase[(j4 * 4 + 1) * HH];
            float w2v = wbase[(j4 * 4 + 2) * HH];
            float w3v = wbase[(j4 * 4 + 3) * HH];
            u64 bp0 = pack2(w0, w1v);
            u64 bp1 = pack2(w2v, w3v);
            #pragma unroll
            for (int rr = 0; rr < 32; rr++) {
                ulonglong2 cc = *(const ulonglong2*)&cs[rr * 32 + j4 * 4];
                acc2[rr] = fma2(cc.x, bp0, acc2[rr]);
                acc2[rr] = fma2(cc.y, bp1, acc2[rr]);
            }
        }
        float wb = W1[(size_t)(32 + i) * HH + h];
        float* dst = g_V + (size_t)(rt * 32) * (DD * HH) + n;
        #pragma unroll
        for (int rr = 0; rr < 32; rr++) {
            float lo, hi; unpack2(acc2[rr], lo, hi);
            dst[(size_t)rr * (DD * HH)] = wb + lo + hi;
        }
    } else if (tid < 64) {
        int h = tid;
        float accs[32];
        float bb = b1[h];
        #pragma unroll
        for (int rr = 0; rr < 32; rr++) accs[rr] = bb;
        #pragma unroll 4
        for (int j = 0; j < 32; j++) {
            float wv = W1[(size_t)j * HH + h];
            #pragma unroll
            for (int rr = 0; rr < 32; rr++)
                accs[rr] = fmaf(cs[rr * 32 + j], wv, accs[rr]);
        }
        float* dst = g_CA + rt * 32 * HH + h;
        #pragma unroll
        for (int rr = 0; rr < 32; rr++) dst[rr * HH] = accs[rr];
    }
}

// ---------------------------------------------------------------------------
// Kernel B: persistent blocks, cp.async double-buffered candidate pipeline.
// Each block handles candidates r = bid, bid+PGRID, ... While computing
// candidate r from buffer `buf`, the next candidate's V/CA/first-tile are
// prefetched into buf^1 via cp.async (zero register staging, latency hidden).
// ---------------------------------------------------------------------------
__global__ void __launch_bounds__(128, 6) attn_main(
    const float* __restrict__ behavior,
    const float* __restrict__ alpha,
    const float* __restrict__ W2,
    const float* __restrict__ b2,
    float* __restrict__ out)
{
    __shared__ __align__(16) float Vs[2][DD * HH];   // 16 KB
    __shared__ __align__(16) float bs[2][64 * BSTRIDE]; // 16.5 KB
    __shared__ __align__(16) float cas[2][HH];
    __shared__ __align__(16) float As[HH];
    __shared__ __align__(16) float Bsh[HH];
    __shared__ __align__(16) float w2s[HH];
    __shared__ float red1[2][64];
    __shared__ float red2[2][64];
    __shared__ float redw[2][64];
    __shared__ float partial[4][DD];

    int tid  = threadIdx.x;
    int lane = tid & 31;
    int wid  = tid >> 5;
    int pair = wid >> 1;
    int half = wid & 1;
    int row  = pair * 32 + lane;

    // candidate-independent params
    if (tid < 64) {
        float al = alpha[tid];
        As[tid]  = 0.5f * (1.0f + al);
        Bsh[tid] = 0.5f * (1.0f - al);
        w2s[tid] = W2[tid];
    }
    float b2v = b2[0];

    int r = blockIdx.x;
    int start = __ldg(&g_off[r]);
    int end   = __ldg(&g_off[r + 1]);

    // prologue: prefetch candidate r into buffer 0
    {
        const float* vsrc = g_V + (size_t)r * (DD * HH);
        uint32_t vdst = s2u(&Vs[0][0]);
        #pragma unroll
        for (int k = 0; k < 4; k++)
            cpa16(vdst + (k * 128 + tid) * 16, vsrc + (k * 128 + tid) * 4);
        if (tid < 16)
            cpa16(s2u(&cas[0][0]) + tid * 16, g_CA + r * HH + tid * 4);
        int nel = end - start; if (nel > 64) nel = 64;
        nel *= DD;
        uint32_t bdst = s2u(&bs[0][0]);
        const float* bsrc = behavior + (size_t)start * DD;
        for (int idx = tid; idx < nel; idx += 128)
            cpa4(bdst + ((idx >> 5) * BSTRIDE + (idx & 31)) * 4, bsrc + idx);
    }
    CP_COMMIT();

    int buf = 0;
    while (true) {
        int rn = r + PGRID;
        int startN = 0, endN = 0;
        if (rn < NB) { startN = __ldg(&g_off[rn]); endN = __ldg(&g_off[rn + 1]); }

        CP_WAIT0();
        __syncthreads();   // current buffers ready for all; prev candidate fully done

        // prefetch next candidate into buf^1 (overlaps with compute below)
        if (rn < NB) {
            int nb = buf ^ 1;
            const float* vsrc = g_V + (size_t)rn * (DD * HH);
            uint32_t vdst = s2u(&Vs[nb][0]);
            #pragma unroll
            for (int k = 0; k < 4; k++)
                cpa16(vdst + (k * 128 + tid) * 16, vsrc + (k * 128 + tid) * 4);
            if (tid < 16)
                cpa16(s2u(&cas[nb][0]) + tid * 16, g_CA + rn * HH + tid * 4);
            int nel = endN - startN; if (nel > 64) nel = 64;
            nel *= DD;
            uint32_t bdst = s2u(&bs[nb][0]);
            const float* bsrc = behavior + (size_t)startN * DD;
            for (int idx = tid; idx < nel; idx += 128)
                cpa4(bdst + ((idx >> 5) * BSTRIDE + (idx & 31)) * 4, bsrc + idx);
        }
        CP_COMMIT();

        // ---- compute candidate r from `buf` ----
        float accd = 0.f;
        for (int base = start; base < end; base += 64) {
            int nrows = end - base; if (nrows > 64) nrows = 64;

            if (base != start) {
                // rare multi-tile path: plain load into current buffer
                const float4* gsrc = (const float4*)(behavior + (size_t)base * DD);
                int n4 = nrows * 8;
                for (int idx = tid; idx < n4; idx += 128) {
                    float4 v = gsrc[idx];
                    float* d = &bs[buf][(idx >> 3) * BSTRIDE + ((idx & 7) << 2)];
                    d[0] = v.x; d[1] = v.y; d[2] = v.z; d[3] = v.w;
                }
                __syncthreads();
            }

            // matvec over this thread's 32 h
            const float* brow = &bs[buf][row * BSTRIDE];
            u64 x2[16];
            {
                const ulonglong2* cp = (const ulonglong2*)&cas[buf][half * 32];
                #pragma unroll
                for (int pp = 0; pp < 8; pp++) {
                    ulonglong2 v = cp[pp];
                    x2[2*pp] = v.x; x2[2*pp+1] = v.y;
                }
            }
            #pragma unroll
            for (int i = 0; i < DD; i++) {
                float bi = brow[i];
                u64 bb = pack2(bi, bi);
                const ulonglong2* vp = (const ulonglong2*)&Vs[buf][i * HH + half * 32];
                #pragma unroll
                for (int pp = 0; pp < 8; pp++) {
                    ulonglong2 v = vp[pp];
                    x2[2*pp]   = fma2(v.x, bb, x2[2*pp]);
                    x2[2*pp+1] = fma2(v.y, bb, x2[2*pp+1]);
                }
            }

            // one-pass moments over this half
            u64 sa = x2[0], sb = x2[1], sc = x2[2], sd = x2[3];
            u64 qa = fma2(x2[0], x2[0], 0ull), qb = fma2(x2[1], x2[1], 0ull);
            u64 qc = fma2(x2[2], x2[2], 0ull), qd = fma2(x2[3], x2[3], 0ull);
            #pragma unroll
            for (int p = 4; p < 16; p += 4) {
                sa = add2(sa, x2[p]);   sb = add2(sb, x2[p+1]);
                sc = add2(sc, x2[p+2]); sd = add2(sd, x2[p+3]);
                qa = fma2(x2[p],   x2[p],   qa); qb = fma2(x2[p+1], x2[p+1], qb);
                qc = fma2(x2[p+2], x2[p+2], qc); qd = fma2(x2[p+3], x2[p+3], qd);
            }
            u64 st = add2(add2(sa, sb), add2(sc, sd));
            u64 qt = add2(add2(qa, qb), add2(qc, qd));
            float slo, shi, qlo, qhi;
            unpack2(st, slo, shi); unpack2(qt, qlo, qhi);
            red1[half][row] = slo + shi;
            red2[half][row] = qlo + qhi;
            __syncthreads();

            float mean = (red1[0][row] + red1[1][row]) * (1.0f / 64.0f);
            float msq  = (red2[0][row] + red2[1][row]) * (1.0f / 64.0f);
            float var  = msq - mean * mean + EPSF;
            float stdv = sqrtf(var);
            float rinv = __fdividef(1.0f, stdv + EPSF);
            float hr = 0.5f * rinv;
            float hm = -mean * hr;   // p = 0.5 + 0.5*tanh(x*hr + hm)

            float w = 0.f;
            #pragma unroll
            for (int pp = 0; pp < 8; pp++) {
                int hb = half * 32 + pp * 4;
                float4 A4  = *(const float4*)&As[hb];
                float4 B4  = *(const float4*)&Bsh[hb];
                float4 w24 = *(const float4*)&w2s[hb];
                float xa, xb_, xc, xd;
                unpack2(x2[2*pp],   xa, xb_);
                unpack2(x2[2*pp+1], xc, xd);
                { float t = tanh_approx(fmaf(xa,  hr, hm)); w = fmaf(xa  * fmaf(B4.x, t, A4.x), w24.x, w); }
                { float t = tanh_approx(fmaf(xb_, hr, hm)); w = fmaf(xb_ * fmaf(B4.y, t, A4.y), w24.y, w); }
                { float t = tanh_approx(fmaf(xc,  hr, hm)); w = fmaf(xc  * fmaf(B4.z, t, A4.z), w24.z, w); }
                { float t = tanh_approx(fmaf(xd,  hr, hm)); w = fmaf(xd  * fmaf(B4.w, t, A4.w), w24.w, w); }
            }
            redw[half][row] = w;
            __syncthreads();

            // segment-sum epilogue: warp wid handles rows [wid*16, wid*16+16)
            int r0 = wid * 16;
            int r1 = r0 + 16; if (r1 > nrows) r1 = nrows;
            for (int rr = r0; rr < r1; rr++) {
                float wv = redw[0][rr] + redw[1][rr] + b2v;
                accd = fmaf(bs[buf][rr * BSTRIDE + lane], wv, accd);
            }
            __syncthreads();
        }

        partial[wid][lane] = accd;
        __syncthreads();
        if (wid == 0)
            out[(size_t)r * DD + lane] =
                partial[0][lane] + partial[1][lane] + partial[2][lane] + partial[3][lane];

        if (rn >= NB) break;
        r = rn; start = startN; end = endN; buf ^= 1;
    }
}

// ---------------------------------------------------------------------------
extern "C" void kernel_launch(void* const* d_in, const int* in_sizes, int n_in,
                              void* d_out, int out_size) {
    const float* cand    = (const float*)d_in[0];
    const float* behav   = (const float*)d_in[1];
    const int*   row_ids = (const int*)  d_in[2];
    const float* W1      = (const float*)d_in[3];
    const float* b1      = (const float*)d_in[4];
    const float* alphaP  = (const float*)d_in[5];
    const float* W2      = (const float*)d_in[6];
    const float* b2      = (const float*)d_in[7];
    float* out = (float*)d_out;
    int T = in_sizes[2];

    build_offsets<<<(T / 4 + 255) / 256 + 1, 256>>>(row_ids, T);
    precompute_V<<<dim3(128, 17), 128>>>(cand, W1, b1);
    attn_main<<<PGRID, 128>>>(behav, alphaP, W2, b2, out);
}

// round 13
// speedup vs baseline: 1.1861x; 1.1861x over previous
#include <cuda_runtime.h>
#include <cstdint>

#define DD 32
#define HH 64
#define NB 4096
#define EPSF 1e-10f
#define BSTRIDE 33

// Scratch (allocation-free rule: __device__ globals)
__device__ float g_V[(size_t)NB * DD * HH];   // [r][i][h]  33.5 MB
__device__ float g_CA[NB * HH];               // [r][h]
__device__ int   g_off[NB + 1];

typedef unsigned long long u64;

__device__ __forceinline__ u64 fma2(u64 a, u64 b, u64 c) {
    u64 d; asm("fma.rn.f32x2 %0, %1, %2, %3;" : "=l"(d) : "l"(a), "l"(b), "l"(c)); return d;
}
__device__ __forceinline__ u64 add2(u64 a, u64 b) {
    u64 d; asm("add.rn.f32x2 %0, %1, %2;" : "=l"(d) : "l"(a), "l"(b)); return d;
}
__device__ __forceinline__ u64 pack2(float lo, float hi) {
    u64 d; asm("mov.b64 %0, {%1, %2};" : "=l"(d) : "f"(lo), "f"(hi)); return d;
}
__device__ __forceinline__ void unpack2(u64 a, float& lo, float& hi) {
    asm("mov.b64 {%0, %1}, %2;" : "=f"(lo), "=f"(hi) : "l"(a));
}
__device__ __forceinline__ float tanh_approx(float x) {
    float y; asm("tanh.approx.f32 %0, %1;" : "=f"(y) : "f"(x)); return y;
}

// ---------------------------------------------------------------------------
// Kernel C: segment offsets from sorted row_ids (parallel scatter).
// ---------------------------------------------------------------------------
__global__ void build_offsets(const int* __restrict__ row_ids, int T) {
    int t = blockIdx.x * blockDim.x + threadIdx.x;
    if (t >= T) return;
    int r  = row_ids[t];
    int rp = (t == 0) ? -1 : row_ids[t - 1];
    for (int q = rp + 1; q <= r; q++) g_off[q] = t;
    if (t == T - 1) {
        for (int q = r + 1; q <= NB; q++) g_off[q] = T;
    }
}

// ---------------------------------------------------------------------------
// Kernel A: per-candidate precompute (unchanged).
// ---------------------------------------------------------------------------
__global__ void __launch_bounds__(128) precompute_V(
    const float* __restrict__ cand,
    const float* __restrict__ W1,
    const float* __restrict__ b1)
{
    __shared__ __align__(16) float cs[32 * 32];
    int rt  = blockIdx.x;
    int nt  = blockIdx.y;
    int tid = threadIdx.x;

    const float4* csrc = (const float4*)(cand + (size_t)rt * 32 * DD);
    float4* cdst = (float4*)cs;
    cdst[tid]       = csrc[tid];
    cdst[tid + 128] = csrc[tid + 128];
    __syncthreads();

    if (nt < 16) {
        int n = nt * 128 + tid;          // n = i*64 + h
        int i = n >> 6, h = n & 63;
        const float* wbase = W1 + (size_t)(64 + i * 32) * HH + h;

        u64 acc2[32];
        #pragma unroll
        for (int rr = 0; rr < 32; rr++) acc2[rr] = 0ull;

        #pragma unroll
        for (int j4 = 0; j4 < 8; j4++) {
            float w0  = wbase[(j4 * 4 + 0) * HH];
            float w1v = wbase[(j4 * 4 + 1) * HH];
            float w2v = wbase[(j4 * 4 + 2) * HH];
            float w3v = wbase[(j4 * 4 + 3) * HH];
            u64 bp0 = pack2(w0, w1v);
            u64 bp1 = pack2(w2v, w3v);
            #pragma unroll
            for (int rr = 0; rr < 32; rr++) {
                ulonglong2 cc = *(const ulonglong2*)&cs[rr * 32 + j4 * 4];
                acc2[rr] = fma2(cc.x, bp0, acc2[rr]);
                acc2[rr] = fma2(cc.y, bp1, acc2[rr]);
            }
        }
        float wb = W1[(size_t)(32 + i) * HH + h];
        float* dst = g_V + (size_t)(rt * 32) * (DD * HH) + n;
        #pragma unroll
        for (int rr = 0; rr < 32; rr++) {
            float lo, hi; unpack2(acc2[rr], lo, hi);
            dst[(size_t)rr * (DD * HH)] = wb + lo + hi;
        }
    } else if (tid < 64) {
        int h = tid;
        float accs[32];
        float bb = b1[h];
        #pragma unroll
        for (int rr = 0; rr < 32; rr++) accs[rr] = bb;
        #pragma unroll 4
        for (int j = 0; j < 32; j++) {
            float wv = W1[(size_t)j * HH + h];
            #pragma unroll
            for (int rr = 0; rr < 32; rr++)
                accs[rr] = fmaf(cs[rr * 32 + j], wv, accs[rr]);
        }
        float* dst = g_CA + rt * 32 * HH + h;
        #pragma unroll
        for (int rr = 0; rr < 32; rr++) dst[rr * HH] = accs[rr];
    }
}

// ---------------------------------------------------------------------------
// Kernel B: quarter-split. 128 threads / block, 1 block per candidate.
// Warp q owns h-quarter [q*16, q*16+16). Lane owns rows {lane, lane+32}.
// Vs LDS amortized over 2 rows; x2 = 16 u64; target 64 regs -> 8 blocks/SM.
// ---------------------------------------------------------------------------
__global__ void __launch_bounds__(128, 8) attn_main(
    const float* __restrict__ behavior,
    const float* __restrict__ alpha,
    const float* __restrict__ W2,
    const float* __restrict__ b2,
    float* __restrict__ out)
{
    __shared__ __align__(16) float Vs[DD * HH];     // 8 KB
    __shared__ float bs[64 * BSTRIDE];              // 8.25 KB
    __shared__ __align__(16) float cas[HH];
    __shared__ __align__(16) float As[HH];          // 0.5*(1+alpha)
    __shared__ __align__(16) float Bsh[HH];         // 0.5*(1-alpha)
    __shared__ __align__(16) float w2s[HH];
    __shared__ float red1[4][64];                   // sum x    [quarter][row]
    __shared__ float red2[4][64];                   // sum x^2
    __shared__ float redw[4][64];                   // partial w
    __shared__ float partial[4][DD];

    int tid  = threadIdx.x;
    int lane = tid & 31;
    int q    = tid >> 5;        // warp = h-quarter
    int row0 = lane;
    int row1 = lane + 32;
    int hb0  = q * 16;          // this warp's h base

    int r = blockIdx.x;

    // segment bounds issued first (latency overlaps staging)
    int start = __ldg(&g_off[r]);
    int end   = __ldg(&g_off[r + 1]);
    float b2v = b2[0];

    // stage V[r] + params
    {
        const float4* src = (const float4*)(g_V + (size_t)r * (DD * HH));
        float4* dst = (float4*)Vs;
        #pragma unroll
        for (int k = 0; k < 4; k++) dst[k * 128 + tid] = src[k * 128 + tid];
        if (tid < 64) {
            cas[tid] = g_CA[r * HH + tid];
            float al = alpha[tid];
            As[tid]  = 0.5f * (1.0f + al);
            Bsh[tid] = 0.5f * (1.0f - al);
            w2s[tid] = W2[tid];
        }
    }

    // first behavior tile load merged into setup (no zero-fill: invalid rows
    // never reach the epilogue sums)
    {
        int nrows0 = end - start; if (nrows0 > 64) nrows0 = 64;
        const float4* gsrc = (const float4*)(behavior + (size_t)start * DD);
        int n4 = nrows0 * 8;
        for (int idx = tid; idx < n4; idx += 128) {
            float4 v = gsrc[idx];
            float* d = &bs[(idx >> 3) * BSTRIDE + ((idx & 7) << 2)];
            d[0] = v.x; d[1] = v.y; d[2] = v.z; d[3] = v.w;
        }
    }
    __syncthreads();

    float accd = 0.f;   // lane owns output dim d = lane; warp owns 16-row slice

    for (int base = start; base < end; base += 64) {
        int nrows = end - base; if (nrows > 64) nrows = 64;

        if (base != start) {
            const float4* gsrc = (const float4*)(behavior + (size_t)base * DD);
            int n4 = nrows * 8;
            for (int idx = tid; idx < n4; idx += 128) {
                float4 v = gsrc[idx];
                float* d = &bs[(idx >> 3) * BSTRIDE + ((idx & 7) << 2)];
                d[0] = v.x; d[1] = v.y; d[2] = v.z; d[3] = v.w;
            }
            __syncthreads();
        }

        // ---- matvec: 2 rows x 16 h per thread; Vs loads shared by both rows ----
        u64 x2[16];   // [0..7] row0, [8..15] row1
        {
            const u64* cu = (const u64*)&cas[hb0];
            #pragma unroll
            for (int p = 0; p < 8; p++) { x2[p] = cu[p]; x2[8 + p] = cu[p]; }
        }
        const float* br0 = &bs[row0 * BSTRIDE];
        const float* br1 = &bs[row1 * BSTRIDE];
        #pragma unroll
        for (int i = 0; i < DD; i++) {
            u64 bb0 = pack2(br0[i], br0[i]);
            u64 bb1 = pack2(br1[i], br1[i]);
            const ulonglong2* vp = (const ulonglong2*)&Vs[i * HH + hb0];
            #pragma unroll
            for (int pp = 0; pp < 4; pp++) {
                ulonglong2 v = vp[pp];
                x2[2*pp]       = fma2(v.x, bb0, x2[2*pp]);
                x2[2*pp+1]     = fma2(v.y, bb0, x2[2*pp+1]);
                x2[8 + 2*pp]   = fma2(v.x, bb1, x2[8 + 2*pp]);
                x2[8 + 2*pp+1] = fma2(v.y, bb1, x2[8 + 2*pp+1]);
            }
        }

        // ---- one-pass moments per row over this quarter (16 h) ----
        #pragma unroll
        for (int rr2 = 0; rr2 < 2; rr2++) {
            const u64* xr = &x2[rr2 * 8];
            u64 s0 = add2(xr[0], xr[1]), s1 = add2(xr[2], xr[3]);
            u64 s2 = add2(xr[4], xr[5]), s3 = add2(xr[6], xr[7]);
            u64 q0 = fma2(xr[0], xr[0], 0ull); q0 = fma2(xr[1], xr[1], q0);
            u64 q1 = fma2(xr[2], xr[2], 0ull); q1 = fma2(xr[3], xr[3], q1);
            u64 q2 = fma2(xr[4], xr[4], 0ull); q2 = fma2(xr[5], xr[5], q2);
            u64 q3 = fma2(xr[6], xr[6], 0ull); q3 = fma2(xr[7], xr[7], q3);
            u64 st = add2(add2(s0, s1), add2(s2, s3));
            u64 qt = add2(add2(q0, q1), add2(q2, q3));
            float slo, shi, qlo, qhi;
            unpack2(st, slo, shi); unpack2(qt, qlo, qhi);
            int rw = rr2 ? row1 : row0;
            red1[q][rw] = slo + shi;
            red2[q][rw] = qlo + qhi;
        }
        __syncthreads();

        // ---- per-row stats (each lane: its two rows) ----
        float w01[2];
        #pragma unroll
        for (int rr2 = 0; rr2 < 2; rr2++) {
            int rw = rr2 ? row1 : row0;
            float mean = (red1[0][rw] + red1[1][rw] + red1[2][rw] + red1[3][rw]) * (1.0f / 64.0f);
            float msq  = (red2[0][rw] + red2[1][rw] + red2[2][rw] + red2[3][rw]) * (1.0f / 64.0f);
            float var  = msq - mean * mean + EPSF;
            float stdv = sqrtf(var);
            float rinv = __fdividef(1.0f, stdv + EPSF);
            float hr = 0.5f * rinv;
            float hm = -mean * hr;   // p = 0.5 + 0.5*tanh(x*hr + hm)

            const u64* xr = &x2[rr2 * 8];
            float w = 0.f;
            #pragma unroll
            for (int pp = 0; pp < 4; pp++) {
                float4 A4  = *(const float4*)&As[hb0 + pp * 4];
                float4 B4  = *(const float4*)&Bsh[hb0 + pp * 4];
                float4 w24 = *(const float4*)&w2s[hb0 + pp * 4];
                float xa, xb_, xc, xd;
                unpack2(xr[2*pp],   xa, xb_);
                unpack2(xr[2*pp+1], xc, xd);
                { float t = tanh_approx(fmaf(xa,  hr, hm)); w = fmaf(xa  * fmaf(B4.x, t, A4.x), w24.x, w); }
                { float t = tanh_approx(fmaf(xb_, hr, hm)); w = fmaf(xb_ * fmaf(B4.y, t, A4.y), w24.y, w); }
                { float t = tanh_approx(fmaf(xc,  hr, hm)); w = fmaf(xc  * fmaf(B4.z, t, A4.z), w24.z, w); }
                { float t = tanh_approx(fmaf(xd,  hr, hm)); w = fmaf(xd  * fmaf(B4.w, t, A4.w), w24.w, w); }
            }
            w01[rr2] = w;
        }
        redw[q][row0] = w01[0];
        redw[q][row1] = w01[1];
        __syncthreads();

        // ---- segment-sum epilogue: warp q handles rows [q*16, q*16+16) ----
        int r0 = q * 16;
        int r1 = r0 + 16; if (r1 > nrows) r1 = nrows;
        for (int rr = r0; rr < r1; rr++) {
            float wv = redw[0][rr] + redw[1][rr] + redw[2][rr] + redw[3][rr] + b2v;
            accd = fmaf(bs[rr * BSTRIDE + lane], wv, accd);
        }
        __syncthreads();   // bs/red reuse next tile
    }

    partial[q][lane] = accd;
    __syncthreads();
    if (q == 0)
        out[(size_t)r * DD + lane] =
            partial[0][lane] + partial[1][lane] + partial[2][lane] + partial[3][lane];
}

// ---------------------------------------------------------------------------
extern "C" void kernel_launch(void* const* d_in, const int* in_sizes, int n_in,
                              void* d_out, int out_size) {
    const float* cand    = (const float*)d_in[0];
    const float* behav   = (const float*)d_in[1];
    const int*   row_ids = (const int*)  d_in[2];
    const float* W1      = (const float*)d_in[3];
    const float* b1      = (const float*)d_in[4];
    const float* alphaP  = (const float*)d_in[5];
    const float* W2      = (const float*)d_in[6];
    const float* b2      = (const float*)d_in[7];
    float* out = (float*)d_out;
    int T = in_sizes[2];

    build_offsets<<<(T + 255) / 256, 256>>>(row_ids, T);
    precompute_V<<<dim3(128, 17), 128>>>(cand, W1, b1);
    attn_main<<<NB, 128>>>(behav, alphaP, W2, b2, out);
}

// round 17
// speedup vs baseline: 1.2156x; 1.0248x over previous
#include <cuda_runtime.h>
#include <cstdint>

#define DD 32
#define HH 64
#define NB 4096
#define EPSF 1e-10f
#define BSTRIDE 36   // 16B-aligned rows; LDS.128 phase-conflict-free (144B lane stride)

// Scratch (allocation-free rule: __device__ globals)
__device__ float g_V[(size_t)NB * DD * HH];   // [r][i][h]  33.5 MB
__device__ float g_CA[NB * HH];               // [r][h]
__device__ int   g_off[NB + 1];

typedef unsigned long long u64;

__device__ __forceinline__ u64 fma2(u64 a, u64 b, u64 c) {
    u64 d; asm("fma.rn.f32x2 %0, %1, %2, %3;" : "=l"(d) : "l"(a), "l"(b), "l"(c)); return d;
}
__device__ __forceinline__ u64 add2(u64 a, u64 b) {
    u64 d; asm("add.rn.f32x2 %0, %1, %2;" : "=l"(d) : "l"(a), "l"(b)); return d;
}
__device__ __forceinline__ u64 pack2(float lo, float hi) {
    u64 d; asm("mov.b64 %0, {%1, %2};" : "=l"(d) : "f"(lo), "f"(hi)); return d;
}
__device__ __forceinline__ void unpack2(u64 a, float& lo, float& hi) {
    asm("mov.b64 {%0, %1}, %2;" : "=f"(lo), "=f"(hi) : "l"(a));
}
__device__ __forceinline__ float tanh_approx(float x) {
    float y; asm("tanh.approx.f32 %0, %1;" : "=f"(y) : "f"(x)); return y;
}

// ---------------------------------------------------------------------------
// Kernel A: per-candidate precompute + (nt==17) offsets scatter, one launch.
//   grid (128, 18), 128 threads.
//   nt<16 : V[r,i,h] = W1[(32+i),h] + sum_j c[r,j] * W1[64+i*32+j, h]
//   nt==16: CA[r,h]  = b1[h] + sum_j c[r,j] * W1[j, h]
//   nt==17: g_off[q] = lower_bound(row_ids, q)   (parallel scatter)
// ---------------------------------------------------------------------------
__global__ void __launch_bounds__(128) precompute_V(
    const float* __restrict__ cand,
    const float* __restrict__ W1,
    const float* __restrict__ b1,
    const int*   __restrict__ row_ids,
    int T)
{
    __shared__ __align__(16) float cs[32 * 32];
    int rt  = blockIdx.x;
    int nt  = blockIdx.y;
    int tid = threadIdx.x;

    if (nt == 17) {
        // offsets scatter, strided over all 128*128 threads of this slice
        int gid = rt * 128 + tid;
        for (int t = gid; t < T; t += 128 * 128) {
            int r  = __ldg(&row_ids[t]);
            int rp = (t == 0) ? -1 : __ldg(&row_ids[t - 1]);
            for (int q = rp + 1; q <= r; q++) g_off[q] = t;
            if (t == T - 1)
                for (int q = r + 1; q <= NB; q++) g_off[q] = T;
        }
        return;
    }

    const float4* csrc = (const float4*)(cand + (size_t)rt * 32 * DD);
    float4* cdst = (float4*)cs;
    cdst[tid]       = csrc[tid];
    cdst[tid + 128] = csrc[tid + 128];
    __syncthreads();

    if (nt < 16) {
        int n = nt * 128 + tid;          // n = i*64 + h
        int i = n >> 6, h = n & 63;
        const float* wbase = W1 + (size_t)(64 + i * 32) * HH + h;

        u64 acc2[32];
        #pragma unroll
        for (int rr = 0; rr < 32; rr++) acc2[rr] = 0ull;

        #pragma unroll
        for (int j4 = 0; j4 < 8; j4++) {
            float w0  = wbase[(j4 * 4 + 0) * HH];
            float w1v = wbase[(j4 * 4 + 1) * HH];
            float w2v = wbase[(j4 * 4 + 2) * HH];
            float w3v = wbase[(j4 * 4 + 3) * HH];
            u64 bp0 = pack2(w0, w1v);
            u64 bp1 = pack2(w2v, w3v);
            #pragma unroll
            for (int rr = 0; rr < 32; rr++) {
                ulonglong2 cc = *(const ulonglong2*)&cs[rr * 32 + j4 * 4];
                acc2[rr] = fma2(cc.x, bp0, acc2[rr]);
                acc2[rr] = fma2(cc.y, bp1, acc2[rr]);
            }
        }
        float wb = W1[(size_t)(32 + i) * HH + h];
        float* dst = g_V + (size_t)(rt * 32) * (DD * HH) + n;
        #pragma unroll
        for (int rr = 0; rr < 32; rr++) {
            float lo, hi; unpack2(acc2[rr], lo, hi);
            dst[(size_t)rr * (DD * HH)] = wb + lo + hi;
        }
    } else if (tid < 64) {
        int h = tid;
        float accs[32];
        float bb = b1[h];
        #pragma unroll
        for (int rr = 0; rr < 32; rr++) accs[rr] = bb;
        #pragma unroll 4
        for (int j = 0; j < 32; j++) {
            float wv = W1[(size_t)j * HH + h];
            #pragma unroll
            for (int rr = 0; rr < 32; rr++)
                accs[rr] = fmaf(cs[rr * 32 + j], wv, accs[rr]);
        }
        float* dst = g_CA + rt * 32 * HH + h;
        #pragma unroll
        for (int rr = 0; rr < 32; rr++) dst[rr * HH] = accs[rr];
    }
}

// ---------------------------------------------------------------------------
// Kernel B: quarter-split. 128 threads / block, 1 block per candidate.
// Warp q owns h-quarter [q*16, q*16+16). Lane owns rows {lane, lane+32}.
// b-rows read via LDS.128 (BSTRIDE=36); rsqrt for dice stats.
// ---------------------------------------------------------------------------
__global__ void __launch_bounds__(128, 8) attn_main(
    const float* __restrict__ behavior,
    const float* __restrict__ alpha,
    const float* __restrict__ W2,
    const float* __restrict__ b2,
    float* __restrict__ out)
{
    __shared__ __align__(16) float Vs[DD * HH];     // 8 KB
    __shared__ __align__(16) float bs[64 * BSTRIDE];// 9.2 KB
    __shared__ __align__(16) float cas[HH];
    __shared__ __align__(16) float As[HH];          // 0.5*(1+alpha)
    __shared__ __align__(16) float Bsh[HH];         // 0.5*(1-alpha)
    __shared__ __align__(16) float w2s[HH];
    __shared__ float red1[4][64];                   // sum x    [quarter][row]
    __shared__ float red2[4][64];                   // sum x^2
    __shared__ float redw[4][64];                   // partial w (q0 includes b2)
    __shared__ float partial[4][DD];

    int tid  = threadIdx.x;
    int lane = tid & 31;
    int q    = tid >> 5;        // warp = h-quarter
    int row0 = lane;
    int row1 = lane + 32;
    int hb0  = q * 16;          // this warp's h base

    int r = blockIdx.x;

    // segment bounds issued first (latency overlaps staging)
    int start = __ldg(&g_off[r]);
    int end   = __ldg(&g_off[r + 1]);
    float b2v = b2[0];

    // stage V[r] + params
    {
        const float4* src = (const float4*)(g_V + (size_t)r * (DD * HH));
        float4* dst = (float4*)Vs;
        #pragma unroll
        for (int k = 0; k < 4; k++) dst[k * 128 + tid] = src[k * 128 + tid];
        if (tid < 64) {
            cas[tid] = g_CA[r * HH + tid];
            float al = alpha[tid];
            As[tid]  = 0.5f * (1.0f + al);
            Bsh[tid] = 0.5f * (1.0f - al);
            w2s[tid] = W2[tid];
        }
    }

    // first behavior tile load merged into setup (no zero-fill: invalid rows
    // never reach the epilogue sums)
    {
        int nrows0 = end - start; if (nrows0 > 64) nrows0 = 64;
        const float4* gsrc = (const float4*)(behavior + (size_t)start * DD);
        int n4 = nrows0 * 8;
        for (int idx = tid; idx < n4; idx += 128) {
            float4 v = gsrc[idx];
            *(float4*)&bs[(idx >> 3) * BSTRIDE + ((idx & 7) << 2)] = v;
        }
    }
    __syncthreads();

    float accd = 0.f;   // lane owns output dim d = lane; warp owns 16-row slice

    for (int base = start; base < end; base += 64) {
        int nrows = end - base; if (nrows > 64) nrows = 64;

        if (base != start) {
            const float4* gsrc = (const float4*)(behavior + (size_t)base * DD);
            int n4 = nrows * 8;
            for (int idx = tid; idx < n4; idx += 128) {
                float4 v = gsrc[idx];
                *(float4*)&bs[(idx >> 3) * BSTRIDE + ((idx & 7) << 2)] = v;
            }
            __syncthreads();
        }

        // ---- matvec: 2 rows x 16 h per thread; Vs + b loads all LDS.128 ----
        // x2[p] (p=0..7)  : row0, h = hb0+2p, hb0+2p+1
        // x2[8+p]         : row1, same h pair
        u64 x2[16];
        {
            const u64* cu = (const u64*)&cas[hb0];
            #pragma unroll
            for (int p = 0; p < 8; p++) { x2[p] = cu[p]; x2[8 + p] = cu[p]; }
        }
        const float4* br0v = (const float4*)&bs[row0 * BSTRIDE];
        const float4* br1v = (const float4*)&bs[row1 * BSTRIDE];
        #pragma unroll
        for (int i4 = 0; i4 < 8; i4++) {
            float4 b0 = br0v[i4];
            float4 b1 = br1v[i4];
            #pragma unroll
            for (int k = 0; k < 4; k++) {
                int i = i4 * 4 + k;
                float s0 = (k == 0) ? b0.x : (k == 1) ? b0.y : (k == 2) ? b0.z : b0.w;
                float s1 = (k == 0) ? b1.x : (k == 1) ? b1.y : (k == 2) ? b1.z : b1.w;
                u64 bb0 = pack2(s0, s0);
                u64 bb1 = pack2(s1, s1);
                const ulonglong2* vp = (const ulonglong2*)&Vs[i * HH + hb0];
                #pragma unroll
                for (int pp = 0; pp < 4; pp++) {
                    ulonglong2 v = vp[pp];
                    x2[2*pp]       = fma2(v.x, bb0, x2[2*pp]);
                    x2[2*pp+1]     = fma2(v.y, bb0, x2[2*pp+1]);
                    x2[8 + 2*pp]   = fma2(v.x, bb1, x2[8 + 2*pp]);
                    x2[8 + 2*pp+1] = fma2(v.y, bb1, x2[8 + 2*pp+1]);
                }
            }
        }

        // ---- one-pass moments per row over this quarter (16 h) ----
        #pragma unroll
        for (int rr2 = 0; rr2 < 2; rr2++) {
            const u64* xr = &x2[rr2 * 8];
            u64 s0 = add2(xr[0], xr[1]), s1 = add2(xr[2], xr[3]);
            u64 s2 = add2(xr[4], xr[5]), s3 = add2(xr[6], xr[7]);
            u64 q0 = fma2(xr[0], xr[0], 0ull); q0 = fma2(xr[1], xr[1], q0);
            u64 q1 = fma2(xr[2], xr[2], 0ull); q1 = fma2(xr[3], xr[3], q1);
            u64 q2 = fma2(xr[4], xr[4], 0ull); q2 = fma2(xr[5], xr[5], q2);
            u64 q3 = fma2(xr[6], xr[6], 0ull); q3 = fma2(xr[7], xr[7], q3);
            u64 st = add2(add2(s0, s1), add2(s2, s3));
            u64 qt = add2(add2(q0, q1), add2(q2, q3));
            float slo, shi, qlo, qhi;
            unpack2(st, slo, shi); unpack2(qt, qlo, qhi);
            int rw = rr2 ? row1 : row0;
            red1[q][rw] = slo + shi;
            red2[q][rw] = qlo + qhi;
        }
        __syncthreads();

        // ---- per-row stats (each lane: its two rows) ----
        float w01[2];
        #pragma unroll
        for (int rr2 = 0; rr2 < 2; rr2++) {
            int rw = rr2 ? row1 : row0;
            float mean = (red1[0][rw] + red1[1][rw] + red1[2][rw] + red1[3][rw]) * (1.0f / 64.0f);
            float msq  = (red2[0][rw] + red2[1][rw] + red2[2][rw] + red2[3][rw]) * (1.0f / 64.0f);
            float var  = msq - mean * mean + EPSF;
            // std+1e-10 vs std: below fp32 ulp for std~O(1) -> rsqrt is exact-equivalent
            float rinv = rsqrtf(var);
            float hr = 0.5f * rinv;
            float hm = -mean * hr;   // p = 0.5 + 0.5*tanh(x*hr + hm)

            const u64* xr = &x2[rr2 * 8];
            float w = (q == 0) ? b2v : 0.f;   // fold b2 into quarter 0
            #pragma unroll
            for (int pp = 0; pp < 4; pp++) {
                float4 A4  = *(const float4*)&As[hb0 + pp * 4];
                float4 B4  = *(const float4*)&Bsh[hb0 + pp * 4];
                float4 w24 = *(const float4*)&w2s[hb0 + pp * 4];
                float xa, xb_, xc, xd;
                unpack2(xr[2*pp],   xa, xb_);
                unpack2(xr[2*pp+1], xc, xd);
                { float t = tanh_approx(fmaf(xa,  hr, hm)); w = fmaf(xa  * fmaf(B4.x, t, A4.x), w24.x, w); }
                { float t = tanh_approx(fmaf(xb_, hr, hm)); w = fmaf(xb_ * fmaf(B4.y, t, A4.y), w24.y, w); }
                { float t = tanh_approx(fmaf(xc,  hr, hm)); w = fmaf(xc  * fmaf(B4.z, t, A4.z), w24.z, w); }
                { float t = tanh_approx(fmaf(xd,  hr, hm)); w = fmaf(xd  * fmaf(B4.w, t, A4.w), w24.w, w); }
            }
            w01[rr2] = w;
        }
        redw[q][row0] = w01[0];
        redw[q][row1] = w01[1];
        __syncthreads();

        // ---- segment-sum epilogue: warp q handles rows [q*16, q*16+16) ----
        int r0 = q * 16;
        int r1 = r0 + 16; if (r1 > nrows) r1 = nrows;
        for (int rr = r0; rr < r1; rr++) {
            float wv = (redw[0][rr] + redw[1][rr]) + (redw[2][rr] + redw[3][rr]);
            accd = fmaf(bs[rr * BSTRIDE + lane], wv, accd);
        }
        __syncthreads();   // bs/red reuse next tile
    }

    partial[q][lane] = accd;
    __syncthreads();
    if (q == 0)
        out[(size_t)r * DD + lane] =
            (partial[0][lane] + partial[1][lane]) + (partial[2][lane] + partial[3][lane]);
}

// ---------------------------------------------------------------------------
extern "C" void kernel_launch(void* const* d_in, const int* in_sizes, int n_in,
                              void* d_out, int out_size) {
    const float* cand    = (const float*)d_in[0];
    const float* behav   = (const float*)d_in[1];
    const int*   row_ids = (const int*)  d_in[2];
    const float* W1      = (const float*)d_in[3];
    const float* b1      = (const float*)d_in[4];
    const float* alphaP  = (const float*)d_in[5];
    const float* W2      = (const float*)d_in[6];
    const float* b2      = (const float*)d_in[7];
    float* out = (float*)d_out;
    int T = in_sizes[2];

    precompute_V<<<dim3(128, 18), 128>>>(cand, W1, b1, row_ids, T);
    attn_main<<<NB, 128>>>(behav, alphaP, W2, b2, out);
}